// round 12
// baseline (speedup 1.0000x reference)
#include <cuda_runtime.h>

// out = (U11 ⊗ U10 ⊗ ... ⊗ U0) @ x, x complex (4096, 512).
// kron chain: matrix = kron(U_i, matrix), i=0..11  =>  U_q acts on state bit q.
// Three launches; each applies a 4-qubit group (bits qb..qb+3) as a register
// butterfly on 16 complex values per thread. Intermediates live in __device__
// global scratch (planar). Final stage writes d_out in a layout chosen from
// out_size, never exceeding out_size * 4 bytes (minimal element size).
// All global accesses are scalar floats and bounds-guarded.

#define DIM    4096
#define BATCH  512
#define LOGB   9
#define NQ     12
#define NELEM  (DIM * BATCH)          // 2097152 complex elements

// Allocation-free planar scratch for intermediate state.
__device__ float g_sr[NELEM];
__device__ float g_si[NELEM];

// src_kind: 0 = planar x (xr, xi), 1 = interleaved complex x (xr), 2 = scratch
// dst_kind: 0 = scratch, 1 = d_out interleaved complex, 2 = d_out real-only
__global__ __launch_bounds__(256)
void qstage(const float* __restrict__ params,
            const float* __restrict__ xr,
            const float* __restrict__ xi,
            float* __restrict__ out,
            int qb, int src_kind, int dst_kind,
            long long cap_floats)             // capacity of `out` in floats
{
    const int t = blockIdx.x * blockDim.x + threadIdx.x;   // 0 .. 131071
    if (t >= (DIM / 16) * BATCH) return;

    const int b  = t & (BATCH - 1);
    const int s  = t >> LOGB;                 // 0 .. 255
    const int lo = s & ((1 << qb) - 1);
    const int hi = s >> qb;

    // ---- 4 gates for this group (registers) ----
    float g00r[4], g00i[4], g01r[4], g01i[4];
    float g10r[4], g10i[4], g11r[4], g11i[4];
#pragma unroll
    for (int j = 0; j < 4; j++) {
        const int q  = qb + j;                // < 12; host checked params >= 36 floats
        const float th = params[q * 3 + 0];
        const float ph = params[q * 3 + 1];
        const float la = params[q * 3 + 2];
        const float c  = cosf(th * 0.5f);
        const float sn = sinf(th * 0.5f);
        const float cl = cosf(la), sl = sinf(la);
        const float cp = cosf(ph), sp = sinf(ph);
        g00r[j] = c;          g00i[j] = 0.0f;
        g01r[j] = -cl * sn;   g01i[j] = -sl * sn;
        g10r[j] = cp * sn;    g10i[j] = sp * sn;
        const float cpl = cp * cl - sp * sl;
        const float spl = sp * cl + cp * sl;
        g11r[j] = cpl * c;    g11i[j] = spl * c;
    }

    // ---- load 16 complex values (scalar, guarded) ----
    float vr[16], vi[16];
#pragma unroll
    for (int m = 0; m < 16; m++) {
        const int c    = (hi << (qb + 4)) | (m << qb) | lo;   // state index, bijective
        const int gidx = c * BATCH + b;
        float ar = 0.0f, ai = 0.0f;
        if (gidx >= 0 && gidx < NELEM) {
            if (src_kind == 0)      { ar = xr[gidx];         ai = xi[gidx]; }
            else if (src_kind == 1) { ar = xr[2 * gidx];     ai = xr[2 * gidx + 1]; }
            else                    { ar = g_sr[gidx];       ai = g_si[gidx]; }
        }
        vr[m] = ar;  vi[m] = ai;
    }

    // ---- butterfly over the 4 local bits ----
#pragma unroll
    for (int j = 0; j < 4; j++) {
        const float u00r = g00r[j], u00i = g00i[j];
        const float u01r = g01r[j], u01i = g01i[j];
        const float u10r = g10r[j], u10i = g10i[j];
        const float u11r = g11r[j], u11i = g11i[j];
#pragma unroll
        for (int m = 0; m < 16; m++) {
            if ((m >> j) & 1) continue;
            const int m1 = m | (1 << j);
            const float ar = vr[m],  ai = vi[m];
            const float br = vr[m1], bi = vi[m1];
            vr[m]  = u00r * ar - u00i * ai + u01r * br - u01i * bi;
            vi[m]  = u00r * ai + u00i * ar + u01r * bi + u01i * br;
            vr[m1] = u10r * ar - u10i * ai + u11r * br - u11i * bi;
            vi[m1] = u10r * ai + u10i * ar + u11r * bi + u11i * br;
        }
    }

    // ---- store 16 complex values (scalar, guarded) ----
#pragma unroll
    for (int m = 0; m < 16; m++) {
        const int c    = (hi << (qb + 4)) | (m << qb) | lo;
        const int gidx = c * BATCH + b;
        if (gidx < 0 || gidx >= NELEM) continue;
        if (dst_kind == 0) {
            g_sr[gidx] = vr[m];
            g_si[gidx] = vi[m];
        } else if (dst_kind == 1) {
            const long long f = 2LL * gidx;
            if (f + 1 < cap_floats) {
                out[f]     = vr[m];
                out[f + 1] = vi[m];
            }
        } else {
            if ((long long)gidx < cap_floats)
                out[gidx] = vr[m];
        }
    }
}

extern "C" void kernel_launch(void* const* d_in, const int* in_sizes, int n_in,
                              void* d_out, int out_size)
{
    // Identify buffers by size, never by position.
    int pidx = -1;
    for (int i = 0; i < n_in; i++)
        if (pidx < 0 || in_sizes[i] < in_sizes[pidx]) pidx = i;
    if (pidx < 0 || in_sizes[pidx] < NQ * 3) return;      // -> "0 nodes" diagnostic
    const float* params = (const float*)d_in[pidx];

    const float* big0 = 0;
    const float* big1 = 0;
    int size0 = 0;
    int nbig = 0;
    for (int i = 0; i < n_in; i++) {
        if (i == pidx) continue;
        if (in_sizes[i] >= NELEM) {
            if (nbig == 0) { big0 = (const float*)d_in[i]; size0 = in_sizes[i]; }
            else if (nbig == 1) big1 = (const float*)d_in[i];
            nbig++;
        }
    }
    if (!big0 || !d_out) return;                          // -> "0 nodes" diagnostic

    const float* xr;
    const float* xi;
    int src0;
    if (nbig >= 2) { xr = big0; xi = big1; src0 = 0; }    // planar real, imag
    else {
        if (size0 < 2 * NELEM) return;                    // cannot interpret safely
        xr = big0; xi = big0; src0 = 1;                   // interleaved complex
    }

    // Output layout from out_size, capacity assuming MINIMAL (4-byte) elements
    // so we can never overrun regardless of the true dtype.
    //   out_size >= 2*NELEM : interleaved complex floats (covers complex64-in-bytes
    //                         and float32-pair views)
    //   otherwise           : real-part-only float32, capped at out_size floats
    int dst_kind;
    long long cap_floats;
    const long long os = (long long)out_size;
    if (os >= 2LL * NELEM) { dst_kind = 1; cap_floats = 2LL * NELEM; }
    else                   { dst_kind = 2; cap_floats = (os < NELEM) ? os : NELEM; }

    float* out = (float*)d_out;

    const int total = (DIM / 16) * BATCH;                 // 131072 threads
    const int blk   = 256;
    const int grd   = (total + blk - 1) / blk;            // 512 blocks

    qstage<<<grd, blk>>>(params, xr, xi, out, 0, src0, 0, 0);          // x   -> scr
    qstage<<<grd, blk>>>(params, 0,  0,  out, 4, 2,    0, 0);          // scr -> scr
    qstage<<<grd, blk>>>(params, 0,  0,  out, 8, 2, dst_kind, cap_floats); // scr -> out
}

// round 13
// speedup vs baseline: 1.3754x; 1.3754x over previous
#include <cuda_runtime.h>

// out = (U11 ⊗ U10 ⊗ ... ⊗ U0) @ x, x complex (4096, 512).
// kron chain: matrix = kron(U_i, matrix), i=0..11  =>  U_q acts on state bit q.
// Prelude kernel computes the 12 2x2 gates once into a device table.
// Three stage launches; each applies a 4-qubit group (bits qb..qb+3) as a
// register butterfly on 16 complex values per thread (bijective ownership ->
// race-free). Intermediates in interleaved float2 scratch. Final stage writes
// d_out per out_size-selected layout, never exceeding out_size*4 bytes.

#define DIM    4096
#define BATCH  512
#define LOGB   9
#define NQ     12
#define NELEM  (DIM * BATCH)          // 2097152 complex elements

// Allocation-free scratch (interleaved complex) + gate table.
__device__ float2 g_scr[NELEM];
__device__ float2 g_gates[NQ * 4];    // [q][0..3] = u00, u01, u10, u11

__global__ void compute_gates_kernel(const float* __restrict__ params)
{
    const int q = threadIdx.x;
    if (q >= NQ) return;
    const float th = params[q * 3 + 0];
    const float ph = params[q * 3 + 1];
    const float la = params[q * 3 + 2];
    float sn, c;  sincosf(th * 0.5f, &sn, &c);
    float sl, cl; sincosf(la, &sl, &cl);
    float sp, cp; sincosf(ph, &sp, &cp);
    // U = [[c, -e^{i la} s], [e^{i ph} s, e^{i(ph+la)} c]]
    g_gates[q * 4 + 0] = make_float2(c, 0.0f);
    g_gates[q * 4 + 1] = make_float2(-cl * sn, -sl * sn);
    g_gates[q * 4 + 2] = make_float2(cp * sn, sp * sn);
    const float cpl = cp * cl - sp * sl;
    const float spl = sp * cl + cp * sl;
    g_gates[q * 4 + 3] = make_float2(cpl * c, spl * c);
}

// src_kind: 0 = planar x (xr, xi), 1 = interleaved complex x (xr), 2 = scratch
// dst_kind: 0 = scratch, 1 = d_out interleaved complex, 2 = d_out real-only
__global__ __launch_bounds__(256)
void qstage(const float* __restrict__ xr,
            const float* __restrict__ xi,
            float* __restrict__ out,
            int qb, int src_kind, int dst_kind,
            long long cap_floats)             // capacity of `out` in floats
{
    const int t = blockIdx.x * blockDim.x + threadIdx.x;   // 0 .. 131071
    if (t >= (DIM / 16) * BATCH) return;

    const int b  = t & (BATCH - 1);
    const int s  = t >> LOGB;                 // 0 .. 255
    const int lo = s & ((1 << qb) - 1);
    const int hi = s >> qb;

    // ---- load 16 complex values (guarded) ----
    float vr[16], vi[16];
#pragma unroll
    for (int m = 0; m < 16; m++) {
        const int c    = (hi << (qb + 4)) | (m << qb) | lo;   // state index
        const int gidx = c * BATCH + b;
        float ar = 0.0f, ai = 0.0f;
        if (gidx >= 0 && gidx < NELEM) {
            if (src_kind == 0)      { ar = xr[gidx];       ai = xi[gidx]; }
            else if (src_kind == 1) { ar = xr[2 * gidx];   ai = xr[2 * gidx + 1]; }
            else { float2 v = g_scr[gidx]; ar = v.x; ai = v.y; }
        }
        vr[m] = ar;  vi[m] = ai;
    }

    // ---- butterfly over the 4 local bits (gates from table, L1 broadcast) ----
#pragma unroll
    for (int j = 0; j < 4; j++) {
        const float2 u00 = g_gates[(qb + j) * 4 + 0];
        const float2 u01 = g_gates[(qb + j) * 4 + 1];
        const float2 u10 = g_gates[(qb + j) * 4 + 2];
        const float2 u11 = g_gates[(qb + j) * 4 + 3];
#pragma unroll
        for (int m = 0; m < 16; m++) {
            if ((m >> j) & 1) continue;
            const int m1 = m | (1 << j);
            const float ar = vr[m],  ai = vi[m];
            const float br = vr[m1], bi = vi[m1];
            vr[m]  = u00.x * ar - u00.y * ai + u01.x * br - u01.y * bi;
            vi[m]  = u00.x * ai + u00.y * ar + u01.x * bi + u01.y * br;
            vr[m1] = u10.x * ar - u10.y * ai + u11.x * br - u11.y * bi;
            vi[m1] = u10.x * ai + u10.y * ar + u11.x * bi + u11.y * br;
        }
    }

    // ---- store 16 complex values (guarded) ----
#pragma unroll
    for (int m = 0; m < 16; m++) {
        const int c    = (hi << (qb + 4)) | (m << qb) | lo;
        const int gidx = c * BATCH + b;
        if (gidx < 0 || gidx >= NELEM) continue;
        if (dst_kind == 0) {
            g_scr[gidx] = make_float2(vr[m], vi[m]);
        } else if (dst_kind == 1) {
            const long long f = 2LL * gidx;
            if (f + 1 < cap_floats)
                ((float2*)out)[gidx] = make_float2(vr[m], vi[m]);
        } else {
            if ((long long)gidx < cap_floats)
                out[gidx] = vr[m];
        }
    }
}

extern "C" void kernel_launch(void* const* d_in, const int* in_sizes, int n_in,
                              void* d_out, int out_size)
{
    // Identify buffers by size, never by position.
    int pidx = -1;
    for (int i = 0; i < n_in; i++)
        if (pidx < 0 || in_sizes[i] < in_sizes[pidx]) pidx = i;
    if (pidx < 0 || in_sizes[pidx] < NQ * 3) return;      // -> "0 nodes" diagnostic
    const float* params = (const float*)d_in[pidx];

    const float* big0 = 0;
    const float* big1 = 0;
    int size0 = 0;
    int nbig = 0;
    for (int i = 0; i < n_in; i++) {
        if (i == pidx) continue;
        if (in_sizes[i] >= NELEM) {
            if (nbig == 0) { big0 = (const float*)d_in[i]; size0 = in_sizes[i]; }
            else if (nbig == 1) big1 = (const float*)d_in[i];
            nbig++;
        }
    }
    if (!big0 || !d_out) return;                          // -> "0 nodes" diagnostic

    const float* xr;
    const float* xi;
    int src0;
    if (nbig >= 2) { xr = big0; xi = big1; src0 = 0; }    // planar real, imag
    else {
        if (size0 < 2 * NELEM) return;                    // cannot interpret safely
        xr = big0; xi = big0; src0 = 1;                   // interleaved complex
    }

    // Output layout from out_size; capacity assumes minimal 4-byte elements.
    int dst_kind;
    long long cap_floats;
    const long long os = (long long)out_size;
    if (os >= 2LL * NELEM) { dst_kind = 1; cap_floats = 2LL * NELEM; }
    else                   { dst_kind = 2; cap_floats = (os < NELEM) ? os : NELEM; }

    float* out = (float*)d_out;

    const int total = (DIM / 16) * BATCH;                 // 131072 threads
    const int blk   = 256;
    const int grd   = (total + blk - 1) / blk;            // 512 blocks

    compute_gates_kernel<<<1, 32>>>(params);
    qstage<<<grd, blk>>>(xr, xi, out, 0, src0, 0, 0);              // x   -> scr
    qstage<<<grd, blk>>>(0,  0,  out, 4, 2,    0, 0);              // scr -> scr
    qstage<<<grd, blk>>>(0,  0,  out, 8, 2, dst_kind, cap_floats); // scr -> out
}

// round 15
// speedup vs baseline: 1.6945x; 1.2320x over previous
#include <cuda_runtime.h>

// out = Re[(U11 ⊗ U10 ⊗ ... ⊗ U0) @ x], x complex (4096, 512).
// (Harness output is the real part as float32, NELEM elements — established
// by R12/13 passing via the real-only store path and R14's out_size probe.)
// kron chain: matrix = kron(U_i, matrix), i=0..11  =>  U_q acts on state bit q.
// Prelude kernel computes the 12 2x2 gates once into a device table.
// Three template-specialized stage launches; each applies a 4-qubit group
// (bits QB..QB+3) as a register butterfly on 16 complex values per thread
// (bijective ownership -> race-free). Intermediates in interleaved float2
// scratch; final stage writes real parts only.

#define DIM    4096
#define BATCH  512
#define LOGB   9
#define NQ     12
#define NELEM  (DIM * BATCH)          // 2097152 complex elements

// Allocation-free scratch (interleaved complex) + gate table.
__device__ float2 g_scr[NELEM];
__device__ float2 g_gates[NQ * 4];    // [q][0..3] = u00, u01, u10, u11

__global__ void compute_gates_kernel(const float* __restrict__ params)
{
    const int q = threadIdx.x;
    if (q >= NQ) return;
    const float th = params[q * 3 + 0];
    const float ph = params[q * 3 + 1];
    const float la = params[q * 3 + 2];
    float sn, c;  sincosf(th * 0.5f, &sn, &c);
    float sl, cl; sincosf(la, &sl, &cl);
    float sp, cp; sincosf(ph, &sp, &cp);
    // U = [[c, -e^{i la} s], [e^{i ph} s, e^{i(ph+la)} c]]
    g_gates[q * 4 + 0] = make_float2(c, 0.0f);
    g_gates[q * 4 + 1] = make_float2(-cl * sn, -sl * sn);
    g_gates[q * 4 + 2] = make_float2(cp * sn, sp * sn);
    const float cpl = cp * cl - sp * sl;
    const float spl = sp * cl + cp * sl;
    g_gates[q * 4 + 3] = make_float2(cpl * c, spl * c);
}

// SRC: 0 = planar x (xr, xi), 1 = interleaved complex x (xr), 2 = scratch
// DST: 0 = scratch (float2), 1 = out (real part only, float, host-verified)
// For all (QB, s<256, m<16): state index <= 4095, so gidx < NELEM statically.
template <int QB, int SRC, int DST>
__global__ __launch_bounds__(256, 4)
void qstage(const float* __restrict__ xr,
            const float* __restrict__ xi,
            float* __restrict__ out)
{
    const int t = blockIdx.x * blockDim.x + threadIdx.x;   // 0 .. 131071
    const int b  = t & (BATCH - 1);
    const int s  = t >> LOGB;                 // 0 .. 255
    const int lo = s & ((1 << QB) - 1);
    const int hi = s >> QB;
    const int base = (hi << (QB + 4)) | lo;   // state with m-bits zero

    // ---- load 16 complex values ----
    float vr[16], vi[16];
#pragma unroll
    for (int m = 0; m < 16; m++) {
        const int gidx = (base | (m << QB)) * BATCH + b;
        if (SRC == 0)      { vr[m] = xr[gidx];              vi[m] = xi[gidx]; }
        else if (SRC == 1) { const float2 v = ((const float2*)xr)[gidx];
                             vr[m] = v.x;                   vi[m] = v.y; }
        else               { const float2 v = g_scr[gidx];
                             vr[m] = v.x;                   vi[m] = v.y; }
    }

    // ---- butterfly over the 4 local bits (gate table, L1 broadcast) ----
#pragma unroll
    for (int j = 0; j < 4; j++) {
        const float2 u00 = g_gates[(QB + j) * 4 + 0];
        const float2 u01 = g_gates[(QB + j) * 4 + 1];
        const float2 u10 = g_gates[(QB + j) * 4 + 2];
        const float2 u11 = g_gates[(QB + j) * 4 + 3];
#pragma unroll
        for (int m = 0; m < 16; m++) {
            if ((m >> j) & 1) continue;
            const int m1 = m | (1 << j);
            const float ar = vr[m],  ai = vi[m];
            const float br = vr[m1], bi = vi[m1];
            vr[m]  = u00.x * ar - u00.y * ai + u01.x * br - u01.y * bi;
            vi[m]  = u00.x * ai + u00.y * ar + u01.x * bi + u01.y * br;
            vr[m1] = u10.x * ar - u10.y * ai + u11.x * br - u11.y * bi;
            vi[m1] = u10.x * ai + u10.y * ar + u11.x * bi + u11.y * br;
        }
    }

    // ---- store (scratch: float2; final: real part only, coalesced) ----
#pragma unroll
    for (int m = 0; m < 16; m++) {
        const int gidx = (base | (m << QB)) * BATCH + b;
        if (DST == 0) g_scr[gidx] = make_float2(vr[m], vi[m]);
        else          out[gidx]   = vr[m];
    }
}

extern "C" void kernel_launch(void* const* d_in, const int* in_sizes, int n_in,
                              void* d_out, int out_size)
{
    // Identify buffers by size, never by position.
    int pidx = -1;
    for (int i = 0; i < n_in; i++)
        if (pidx < 0 || in_sizes[i] < in_sizes[pidx]) pidx = i;
    if (pidx < 0 || in_sizes[pidx] < NQ * 3) return;      // -> "0 nodes" diagnostic
    const float* params = (const float*)d_in[pidx];

    const float* big0 = 0;
    const float* big1 = 0;
    int size0 = 0;
    int nbig = 0;
    for (int i = 0; i < n_in; i++) {
        if (i == pidx) continue;
        if (in_sizes[i] >= NELEM) {
            if (nbig == 0) { big0 = (const float*)d_in[i]; size0 = in_sizes[i]; }
            else if (nbig == 1) big1 = (const float*)d_in[i];
            nbig++;
        }
    }
    if (!big0 || !d_out) return;                          // -> "0 nodes" diagnostic

    // Output: real part, float32, NELEM elements (established R12-R14).
    if ((long long)out_size < (long long)NELEM) return;   // -> "0 nodes" diagnostic

    float* out = (float*)d_out;
    const int blk = 256;
    const int grd = ((DIM / 16) * BATCH) / blk;           // 512 blocks

    compute_gates_kernel<<<1, 32>>>(params);

    if (nbig >= 2) {                                      // planar real, imag
        qstage<0, 0, 0><<<grd, blk>>>(big0, big1, out);   // x   -> scr
    } else {                                              // single interleaved buffer
        if (size0 < 2 * NELEM) return;
        qstage<0, 1, 0><<<grd, blk>>>(big0, 0, out);      // x   -> scr
    }
    qstage<4, 2, 0><<<grd, blk>>>(0, 0, out);             // scr -> scr
    qstage<8, 2, 1><<<grd, blk>>>(0, 0, out);             // scr -> out (real)
}

// round 16
// speedup vs baseline: 2.2273x; 1.3144x over previous
#include <cuda_runtime.h>

// out = Re[(U11 ⊗ U10 ⊗ ... ⊗ U0) @ x], x complex (4096, 512).
// (Output contract: real part, float32, NELEM elements — established R12–R15.)
// kron chain: matrix = kron(U_i, matrix), i=0..11  =>  U_q acts on state bit q.
//
// TWO stage launches, 6 qubits each (QB=0, then QB=6):
//   phase 1: register butterfly on u-bits 0..3 (u = 6-bit local state index)
//   phase 2: smem exchange remaps u-bits, register butterfly on u-bits 4..5
// Thread holds 16 complex values; CTA tile = 64 states x 32 batch (16 KB smem).
// Gates are computed per-CTA by 6 threads into smem (no prelude kernel).
// Intermediate state in device-global float2 scratch (proven safe R10+).

#define DIM    4096
#define BATCH  512
#define NQ     12
#define NELEM  (DIM * BATCH)          // 2097152 complex elements

__device__ float2 g_scr[NELEM];

// SRC: 0 = planar x (xr, xi), 1 = interleaved complex x (xr), 2 = scratch
// DST: 0 = scratch (float2), 1 = out (real part only, float)
// QB in {0, 6}. blk selects the fixed 6 bits: QB=0 -> hi6=blk (c = blk*64+u),
// QB=6 -> lo6=blk (c = u*64+blk). All indices statically < NELEM.
template <int QB, int SRC, int DST>
__global__ __launch_bounds__(128, 8)
void qstage6(const float* __restrict__ params,
             const float* __restrict__ xr,
             const float* __restrict__ xi,
             float* __restrict__ out)
{
    __shared__ float2 tile[64 * 32];
    __shared__ float2 gs[6 * 4];      // local gates for qubits QB+0 .. QB+5

    const int bl  = threadIdx.x & 31;          // batch lane 0..31
    const int g   = threadIdx.x >> 5;          // u bits [4:6) owner, 0..3
    const int blk = blockIdx.x;                // 0..63 (fixed 6 state bits)
    const int b0  = blockIdx.y * 32;           // batch tile base
    const int base_c = (QB == 0) ? (blk << 6) : blk;

    // ---- gates: 6 threads compute qubits QB..QB+5 into smem ----
    if (threadIdx.x < 6) {
        const int q = QB + threadIdx.x;
        const float th = params[q * 3 + 0];
        const float ph = params[q * 3 + 1];
        const float la = params[q * 3 + 2];
        float sn, c;  sincosf(th * 0.5f, &sn, &c);
        float sl, cl; sincosf(la, &sl, &cl);
        float sp, cp; sincosf(ph, &sp, &cp);
        gs[threadIdx.x * 4 + 0] = make_float2(c, 0.0f);
        gs[threadIdx.x * 4 + 1] = make_float2(-cl * sn, -sl * sn);
        gs[threadIdx.x * 4 + 2] = make_float2(cp * sn, sp * sn);
        const float cpl = cp * cl - sp * sl;
        const float spl = sp * cl + cp * sl;
        gs[threadIdx.x * 4 + 3] = make_float2(cpl * c, spl * c);
    }

    // ---- load 16 complex values: u = g*16 + m  (u bits [0:4) = m) ----
    float vr[16], vi[16];
#pragma unroll
    for (int m = 0; m < 16; m++) {
        const int u    = (g << 4) | m;
        const int gidx = (base_c + (u << QB)) * BATCH + b0 + bl;
        if (SRC == 0)      { vr[m] = xr[gidx];            vi[m] = xi[gidx]; }
        else if (SRC == 1) { const float2 v = ((const float2*)xr)[gidx];
                             vr[m] = v.x;                 vi[m] = v.y; }
        else               { const float2 v = g_scr[gidx];
                             vr[m] = v.x;                 vi[m] = v.y; }
    }

    __syncthreads();   // gates visible (also orders nothing else yet)

    // ---- phase 1: butterfly u-bits 0..3 (= m bits) with gates QB+0..QB+3 ----
#pragma unroll
    for (int j = 0; j < 4; j++) {
        const float2 u00 = gs[j * 4 + 0];
        const float2 u01 = gs[j * 4 + 1];
        const float2 u10 = gs[j * 4 + 2];
        const float2 u11 = gs[j * 4 + 3];
#pragma unroll
        for (int m = 0; m < 16; m++) {
            if ((m >> j) & 1) continue;
            const int m1 = m | (1 << j);
            const float ar = vr[m],  ai = vi[m];
            const float br = vr[m1], bi = vi[m1];
            vr[m]  = u00.x * ar - u00.y * ai + u01.x * br - u01.y * bi;
            vi[m]  = u00.x * ai + u00.y * ar + u01.x * bi + u01.y * br;
            vr[m1] = u10.x * ar - u10.y * ai + u11.x * br - u11.y * bi;
            vi[m1] = u10.x * ai + u10.y * ar + u11.x * bi + u11.y * br;
        }
    }

    // ---- smem exchange: write (u = g*16+m), re-read (u = m2*4+g) ----
#pragma unroll
    for (int m = 0; m < 16; m++)
        tile[(((g << 4) | m) << 5) + bl] = make_float2(vr[m], vi[m]);
    __syncthreads();
#pragma unroll
    for (int m2 = 0; m2 < 16; m2++) {
        const float2 v = tile[(((m2 << 2) | g) << 5) + bl];
        vr[m2] = v.x;  vi[m2] = v.y;
    }
    // now u bits [0:2) = g (done), u bits [2:6) = m2; u bit 4 = m2 bit 2, u bit 5 = m2 bit 3

    // ---- phase 2: butterfly u-bits 4..5 (= m2 bits 2..3), gates QB+4, QB+5 ----
#pragma unroll
    for (int j2 = 2; j2 < 4; j2++) {
        const int jg = j2 + 2;                 // gate slot 4, 5
        const float2 u00 = gs[jg * 4 + 0];
        const float2 u01 = gs[jg * 4 + 1];
        const float2 u10 = gs[jg * 4 + 2];
        const float2 u11 = gs[jg * 4 + 3];
#pragma unroll
        for (int m = 0; m < 16; m++) {
            if ((m >> j2) & 1) continue;
            const int m1 = m | (1 << j2);
            const float ar = vr[m],  ai = vi[m];
            const float br = vr[m1], bi = vi[m1];
            vr[m]  = u00.x * ar - u00.y * ai + u01.x * br - u01.y * bi;
            vi[m]  = u00.x * ai + u00.y * ar + u01.x * bi + u01.y * br;
            vr[m1] = u10.x * ar - u10.y * ai + u11.x * br - u11.y * bi;
            vi[m1] = u10.x * ai + u10.y * ar + u11.x * bi + u11.y * br;
        }
    }

    // ---- store 16 values (u = m2*4 + g mapping) ----
#pragma unroll
    for (int m2 = 0; m2 < 16; m2++) {
        const int u    = (m2 << 2) | g;
        const int gidx = (base_c + (u << QB)) * BATCH + b0 + bl;
        if (DST == 0) g_scr[gidx] = make_float2(vr[m2], vi[m2]);
        else          out[gidx]   = vr[m2];
    }
}

extern "C" void kernel_launch(void* const* d_in, const int* in_sizes, int n_in,
                              void* d_out, int out_size)
{
    // Identify buffers by size, never by position.
    int pidx = -1;
    for (int i = 0; i < n_in; i++)
        if (pidx < 0 || in_sizes[i] < in_sizes[pidx]) pidx = i;
    if (pidx < 0 || in_sizes[pidx] < NQ * 3) return;      // -> "0 nodes" diagnostic
    const float* params = (const float*)d_in[pidx];

    const float* big0 = 0;
    const float* big1 = 0;
    int size0 = 0;
    int nbig = 0;
    for (int i = 0; i < n_in; i++) {
        if (i == pidx) continue;
        if (in_sizes[i] >= NELEM) {
            if (nbig == 0) { big0 = (const float*)d_in[i]; size0 = in_sizes[i]; }
            else if (nbig == 1) big1 = (const float*)d_in[i];
            nbig++;
        }
    }
    if (!big0 || !d_out) return;                          // -> "0 nodes" diagnostic

    // Output: real part, float32, NELEM elements (established R12-R15).
    if ((long long)out_size < (long long)NELEM) return;   // -> "0 nodes" diagnostic

    float* out = (float*)d_out;
    dim3 grid(64, 16);                                    // 1024 CTAs
    dim3 block(128);

    if (nbig >= 2) {                                      // planar real, imag
        qstage6<0, 0, 0><<<grid, block>>>(params, big0, big1, out);  // x -> scr
    } else {                                              // single interleaved buffer
        if (size0 < 2 * NELEM) return;
        qstage6<0, 1, 0><<<grid, block>>>(params, big0, 0, out);     // x -> scr
    }
    qstage6<6, 2, 1><<<grid, block>>>(params, 0, 0, out);            // scr -> out (real)
}

// round 17
// speedup vs baseline: 2.2315x; 1.0019x over previous
#include <cuda_runtime.h>

// out = Re[(U11 ⊗ U10 ⊗ ... ⊗ U0) @ x], x complex (4096, 512).
// Output contract: real part, float32, NELEM elements (established R12-R16).
// kron chain: U_q acts on state bit q. Two stage launches, 6 qubits each
// (QB=0 then QB=6): register butterfly on 4 bits + smem exchange + 2 bits.
//
// NEW vs R16: batch-pair SIMD2. Each thread processes TWO adjacent batch
// columns packed in 64-bit registers; all butterfly math uses fma.rn.f32x2
// (Blackwell packed fp32, PTX-only). All global traffic is ld/st.u64 on
// planar arrays -> zero repacking, fully coalesced (32 lanes x 8B = 256B).
// CTA tile: 64 states x 64 batch; smem exchange in u64, conflict-free.

#define DIM    4096
#define BATCH  512
#define NQ     12
#define NELEM  (DIM * BATCH)          // 2097152 complex elements

typedef unsigned long long u64;

// Planar packed scratch: element si = c*256 + b/2 holds batch pair (b, b+1).
__device__ u64 g_scr_r[NELEM / 2];
__device__ u64 g_scr_i[NELEM / 2];

__device__ __forceinline__ u64 pack2(float lo, float hi) {
    u64 r; asm("mov.b64 %0, {%1, %2};" : "=l"(r) : "f"(lo), "f"(hi)); return r;
}
__device__ __forceinline__ u64 bcast2(float v) { return pack2(v, v); }
__device__ __forceinline__ u64 mul2(u64 a, u64 b) {
    u64 d; asm("mul.rn.f32x2 %0, %1, %2;" : "=l"(d) : "l"(a), "l"(b)); return d;
}
__device__ __forceinline__ u64 fma2(u64 a, u64 b, u64 c) {
    u64 d; asm("fma.rn.f32x2 %0, %1, %2, %3;" : "=l"(d) : "l"(a), "l"(b), "l"(c)); return d;
}

// One 2x2 complex gate applied to packed pair (a, b) -> overwrites in place.
// Coefficients pre-broadcast; ny* = -y broadcast.
__device__ __forceinline__ void bfly(u64& ar, u64& ai, u64& br, u64& bi,
                                     u64 x00, u64 y00, u64 n00,
                                     u64 x01, u64 y01, u64 n01,
                                     u64 x10, u64 y10, u64 n10,
                                     u64 x11, u64 y11, u64 n11) {
    const u64 nr0 = fma2(n01, bi, fma2(x01, br, fma2(n00, ai, mul2(x00, ar))));
    const u64 ni0 = fma2(y01, br, fma2(x01, bi, fma2(y00, ar, mul2(x00, ai))));
    const u64 nr1 = fma2(n11, bi, fma2(x11, br, fma2(n10, ai, mul2(x10, ar))));
    const u64 ni1 = fma2(y11, br, fma2(x11, bi, fma2(y10, ar, mul2(x10, ai))));
    ar = nr0; ai = ni0; br = nr1; bi = ni1;
}

// SRC: 0 = planar x (xr, xi), 1 = interleaved complex x (xr), 2 = scratch
// DST: 0 = scratch, 1 = out (real part only, two floats per st.u64)
// QB in {0, 6}; blk fixes the other 6 state bits. All indices static < NELEM.
template <int QB, int SRC, int DST>
__global__ __launch_bounds__(128, 4)
void qstage6(const float* __restrict__ params,
             const float* __restrict__ xr,
             const float* __restrict__ xi,
             float* __restrict__ out)
{
    __shared__ u64   tr[64 * 32];     // 16 KB: packed real, [state u][bl2]
    __shared__ u64   ti[64 * 32];     // 16 KB: packed imag
    __shared__ float2 gs[6 * 4];      // gates for qubits QB+0 .. QB+5

    const int bl2 = threadIdx.x & 31;          // batch-pair lane 0..31
    const int g   = threadIdx.x >> 5;          // 0..3
    const int blk = blockIdx.x;                // 0..63
    const int b0  = blockIdx.y * 64;           // batch tile base (64 wide)
    const int base_c = (QB == 0) ? (blk << 6) : blk;
    const int boff = b0 + bl2 * 2;             // even float offset

    if (threadIdx.x < 6) {
        const int q = QB + threadIdx.x;
        const float th = params[q * 3 + 0];
        const float ph = params[q * 3 + 1];
        const float la = params[q * 3 + 2];
        float sn, c;  sincosf(th * 0.5f, &sn, &c);
        float sl, cl; sincosf(la, &sl, &cl);
        float sp, cp; sincosf(ph, &sp, &cp);
        gs[threadIdx.x * 4 + 0] = make_float2(c, 0.0f);
        gs[threadIdx.x * 4 + 1] = make_float2(-cl * sn, -sl * sn);
        gs[threadIdx.x * 4 + 2] = make_float2(cp * sn, sp * sn);
        const float cpl = cp * cl - sp * sl;
        const float spl = sp * cl + cp * sl;
        gs[threadIdx.x * 4 + 3] = make_float2(cpl * c, spl * c);
    }

    // ---- load 16 packed complex pairs: u = g*16 + m ----
    u64 vr[16], vi[16];
#pragma unroll
    for (int m = 0; m < 16; m++) {
        const int u    = (g << 4) | m;
        const int c    = base_c + (u << QB);
        const int fidx = c * BATCH + boff;     // even -> 8B aligned
        if (SRC == 0) {
            vr[m] = *(const u64*)(xr + fidx);  // (r0, r1) packed
            vi[m] = *(const u64*)(xi + fidx);
        } else if (SRC == 1) {
            const float4 v = *(const float4*)(xr + 2 * fidx); // r0,i0,r1,i1
            vr[m] = pack2(v.x, v.z);
            vi[m] = pack2(v.y, v.w);
        } else {
            const int si = c * (BATCH / 2) + (boff >> 1);
            vr[m] = g_scr_r[si];
            vi[m] = g_scr_i[si];
        }
    }

    __syncthreads();   // gates visible

    // ---- phase 1: butterfly u-bits 0..3 (m bits), gates QB+0..QB+3 ----
#pragma unroll
    for (int j = 0; j < 4; j++) {
        const float2 u00 = gs[j * 4 + 0], u01 = gs[j * 4 + 1];
        const float2 u10 = gs[j * 4 + 2], u11 = gs[j * 4 + 3];
        const u64 x00 = bcast2(u00.x), y00 = bcast2(u00.y), n00 = bcast2(-u00.y);
        const u64 x01 = bcast2(u01.x), y01 = bcast2(u01.y), n01 = bcast2(-u01.y);
        const u64 x10 = bcast2(u10.x), y10 = bcast2(u10.y), n10 = bcast2(-u10.y);
        const u64 x11 = bcast2(u11.x), y11 = bcast2(u11.y), n11 = bcast2(-u11.y);
#pragma unroll
        for (int m = 0; m < 16; m++) {
            if ((m >> j) & 1) continue;
            const int m1 = m | (1 << j);
            bfly(vr[m], vi[m], vr[m1], vi[m1],
                 x00, y00, n00, x01, y01, n01, x10, y10, n10, x11, y11, n11);
        }
    }

    // ---- smem exchange: write u = g*16+m, read u = m2*4+g ----
#pragma unroll
    for (int m = 0; m < 16; m++) {
        const int u = (g << 4) | m;
        tr[(u << 5) + bl2] = vr[m];
        ti[(u << 5) + bl2] = vi[m];
    }
    __syncthreads();
#pragma unroll
    for (int m2 = 0; m2 < 16; m2++) {
        const int u = (m2 << 2) | g;
        vr[m2] = tr[(u << 5) + bl2];
        vi[m2] = ti[(u << 5) + bl2];
    }
    // u bits [0:2) = g (done); u bit 4 = m2 bit 2, u bit 5 = m2 bit 3

    // ---- phase 2: butterfly u-bits 4..5, gates QB+4, QB+5 ----
#pragma unroll
    for (int j2 = 2; j2 < 4; j2++) {
        const int jg = j2 + 2;
        const float2 u00 = gs[jg * 4 + 0], u01 = gs[jg * 4 + 1];
        const float2 u10 = gs[jg * 4 + 2], u11 = gs[jg * 4 + 3];
        const u64 x00 = bcast2(u00.x), y00 = bcast2(u00.y), n00 = bcast2(-u00.y);
        const u64 x01 = bcast2(u01.x), y01 = bcast2(u01.y), n01 = bcast2(-u01.y);
        const u64 x10 = bcast2(u10.x), y10 = bcast2(u10.y), n10 = bcast2(-u10.y);
        const u64 x11 = bcast2(u11.x), y11 = bcast2(u11.y), n11 = bcast2(-u11.y);
#pragma unroll
        for (int m = 0; m < 16; m++) {
            if ((m >> j2) & 1) continue;
            const int m1 = m | (1 << j2);
            bfly(vr[m], vi[m], vr[m1], vi[m1],
                 x00, y00, n00, x01, y01, n01, x10, y10, n10, x11, y11, n11);
        }
    }

    // ---- store (u = m2*4 + g mapping) ----
#pragma unroll
    for (int m2 = 0; m2 < 16; m2++) {
        const int u    = (m2 << 2) | g;
        const int c    = base_c + (u << QB);
        const int fidx = c * BATCH + boff;
        if (DST == 0) {
            const int si = c * (BATCH / 2) + (boff >> 1);
            g_scr_r[si] = vr[m2];
            g_scr_i[si] = vi[m2];
        } else {
            *(u64*)(out + fidx) = vr[m2];      // two real floats
        }
    }
}

extern "C" void kernel_launch(void* const* d_in, const int* in_sizes, int n_in,
                              void* d_out, int out_size)
{
    // Identify buffers by size, never by position.
    int pidx = -1;
    for (int i = 0; i < n_in; i++)
        if (pidx < 0 || in_sizes[i] < in_sizes[pidx]) pidx = i;
    if (pidx < 0 || in_sizes[pidx] < NQ * 3) return;      // -> "0 nodes" diagnostic
    const float* params = (const float*)d_in[pidx];

    const float* big0 = 0;
    const float* big1 = 0;
    int size0 = 0;
    int nbig = 0;
    for (int i = 0; i < n_in; i++) {
        if (i == pidx) continue;
        if (in_sizes[i] >= NELEM) {
            if (nbig == 0) { big0 = (const float*)d_in[i]; size0 = in_sizes[i]; }
            else if (nbig == 1) big1 = (const float*)d_in[i];
            nbig++;
        }
    }
    if (!big0 || !d_out) return;                          // -> "0 nodes" diagnostic

    // Output: real part, float32, NELEM elements (established R12-R16).
    if ((long long)out_size < (long long)NELEM) return;   // -> "0 nodes" diagnostic

    float* out = (float*)d_out;
    dim3 grid(64, 8);                                     // 512 CTAs
    dim3 block(128);

    if (nbig >= 2) {                                      // planar real, imag
        qstage6<0, 0, 0><<<grid, block>>>(params, big0, big1, out);  // x -> scr
    } else {                                              // single interleaved buffer
        if (size0 < 2 * NELEM) return;
        qstage6<0, 1, 0><<<grid, block>>>(params, big0, 0, out);     // x -> scr
    }
    qstage6<6, 2, 1><<<grid, block>>>(params, 0, 0, out);            // scr -> out (real)
}